// round 12
// baseline (speedup 1.0000x reference)
#include <cuda_runtime.h>
#include <math.h>

// Problem constants
#define BB 2
#define NN 512
#define CC 151
#define DD 4096
#define SCORE_THRESH 0.05f
#define NMS_THRESH_F 0.5f
#define TOPN_PER_CLS 300
#define DET_PER_IMG 100
#define W_CLIP 799.0f
#define H_CLIP 599.0f

#define NTASKS (BB*(CC-1))   // 300 NMS tasks

// input element counts (for pointer identification)
#define SZ_LOGITS (BB*NN*CC)       // 154624
#define SZ_REG    (BB*NN*CC*4)     // 618496
#define SZ_PROPS  (BB*NN*4)        // 4096
#define SZ_FEATS  (BB*NN*DD)       // 4194304

// output layout (float32)
#define OFF_BOXES  0
#define OFF_SCORES (BB*NN*4)            // 4096
#define OFF_LABELS (OFF_SCORES + BB*NN) // 5120
#define OFF_VALID  (OFF_LABELS + BB*NN) // 6144
#define OFF_FEATS  (OFF_VALID + BB*NN)  // 7168

// scratch (device globals; no allocation allowed)
__device__ float2 g_msum[BB*NN];                   // per-row (max, 1/sum)
__device__ unsigned long long g_best[BB*NN];       // packed (score_bits<<32)|(CC-label)
__device__ float g_validf[BB*NN];                  // 1.0/0.0 mask for features
__device__ unsigned g_done = 0;                    // NMS completion counter

// ---------------------------------------------------------------------------
// decode stays double (few K calls; feeds output boxes + IoU inputs)
// ---------------------------------------------------------------------------
__device__ __forceinline__ void decode_clip(const float* pb, const float* rg,
                                            float& X1, float& Y1, float& X2, float& Y2)
{
    const double DCLAMP = (double)(float)log(62.5);  // float(np.log(1000/16))
    double x1 = pb[0], y1 = pb[1], x2 = pb[2], y2 = pb[3];
    double w = x2 - x1 + 1.0, h = y2 - y1 + 1.0;
    double cx = x1 + 0.5 * w, cy = y1 + 0.5 * h;
    double dx = (double)rg[0] / 10.0;
    double dy = (double)rg[1] / 10.0;
    double dw = fmin((double)rg[2] / 5.0, DCLAMP);
    double dh = fmin((double)rg[3] / 5.0, DCLAMP);
    double pcx = dx * w + cx, pcy = dy * h + cy;
    double pw = exp(dw) * w, ph = exp(dh) * h;
    float a = (float)(pcx - 0.5 * pw);
    float b = (float)(pcy - 0.5 * ph);
    float c = (float)(pcx + 0.5 * pw - 1.0);
    float d = (float)(pcy + 0.5 * ph - 1.0);
    X1 = fminf(fmaxf(a, 0.f), W_CLIP);
    Y1 = fminf(fmaxf(b, 0.f), H_CLIP);
    X2 = fminf(fmaxf(c, 0.f), W_CLIP);
    Y2 = fminf(fmaxf(d, 0.f), H_CLIP);
}

// float IoU, exact reference formula order (Pascal +1 convention)
__device__ __forceinline__ float iou_f(float ax1, float ay1, float ax2, float ay2, float areaA,
                                       float bx1, float by1, float bx2, float by2, float areaB)
{
    float xx1 = fmaxf(ax1, bx1);
    float yy1 = fmaxf(ay1, by1);
    float xx2 = fminf(ax2, bx2);
    float yy2 = fminf(ay2, by2);
    float inter = fmaxf(xx2 - xx1 + 1.0f, 0.0f) * fmaxf(yy2 - yy1 + 1.0f, 0.0f);
    return inter / (areaA + areaB - inter);
}

__device__ __forceinline__ unsigned long long pack_sl(float s, int c)
{
    return ((unsigned long long)__float_as_uint(s) << 32) | (unsigned)(CC - c);
}

// ---------------------------------------------------------------------------
// K1: per-row softmax reduction -> (max, 1/sum); zero g_best
// ---------------------------------------------------------------------------
__global__ __launch_bounds__(256) void k_reduce(const float* __restrict__ logits)
{
    int gidx = blockIdx.x * 256 + threadIdx.x;
    if (gidx < BB * NN) g_best[gidx] = 0ull;

    int gw = blockIdx.x * 8 + (threadIdx.x >> 5);   // 128 blocks * 8 warps = 1024 rows
    int lane = threadIdx.x & 31;
    if (gw >= BB * NN) return;
    const float* lrow = logits + gw * CC;
    float x[5];
    float m = -INFINITY;
    #pragma unroll
    for (int j = 0; j < 5; j++) {
        int c = lane + 32 * j;
        x[j] = (c < CC) ? lrow[c] : -INFINITY;
        m = fmaxf(m, x[j]);
    }
    #pragma unroll
    for (int s = 16; s > 0; s >>= 1)
        m = fmaxf(m, __shfl_xor_sync(0xffffffffu, m, s));
    float sum = 0.f;
    #pragma unroll
    for (int j = 0; j < 5; j++) {
        int c = lane + 32 * j;
        sum += (c < CC) ? expf(x[j] - m) : 0.f;
    }
    #pragma unroll
    for (int s = 16; s > 0; s >>= 1)
        sum += __shfl_xor_sync(0xffffffffu, sum, s);
    if (lane == 0)
        g_msum[gw] = make_float2(m, 1.f / sum);
}

// ---------------------------------------------------------------------------
// K2: per (b,c) NMS -> atomicMax g_best; LAST block runs the select epilogue
// ---------------------------------------------------------------------------
__global__ __launch_bounds__(512) void k_nms(const float* __restrict__ logits,
                                             const float* __restrict__ reg,
                                             const float* __restrict__ props,
                                             float* __restrict__ out)
{
    int blk = blockIdx.x;           // b*(CC-1) + (c-1)
    int b = blk / (CC - 1), c = blk % (CC - 1) + 1;
    int tid = threadIdx.x;
    int lane = tid & 31;
    int wid = tid >> 5;

    // own-class score from logits + row reduction (identical formula to before)
    float2 ms = g_msum[b * NN + tid];
    float x = logits[(size_t)(b * NN + tid) * CC + c];
    float s = expf(x - ms.x) * ms.y;

    __shared__ int cnt;
    __shared__ float cs[NN];
    __shared__ int   cn[NN];
    __shared__ float bx1[NN], by1[NN], bx2[NN], by2[NN], bar[NN];
    __shared__ short rankOf[NN];
    __shared__ int   ord[NN];
    __shared__ unsigned char keep[NN];
    __shared__ unsigned smask[128][4];
    __shared__ int lastFlag;
    __shared__ float wmin[16];

    if (tid == 0) cnt = 0;
    __syncthreads();

    int slot = -1;
    if (s > SCORE_THRESH) slot = atomicAdd(&cnt, 1);
    if (slot >= 0) { cs[slot] = s; cn[slot] = tid; }
    __syncthreads();

    int M = cnt;

    if (M > 0 && M <= 128) {
        // ---- bitmask path ----------------------------------------------------
        if (tid < M) {
            int n = cn[tid];
            const float* pb = props + (b * NN + n) * 4;
            const float* rg = reg + (size_t)(((b * NN + n) * CC) + c) * 4;
            decode_clip(pb, rg, bx1[tid], by1[tid], bx2[tid], by2[tid]);
            bar[tid] = (bx2[tid] - bx1[tid] + 1.0f) * (by2[tid] - by1[tid] + 1.0f);
            float msc = cs[tid]; int mn = cn[tid];
            int r = 0;
            for (int j = 0; j < M; j++) {
                float sj = cs[j]; int nj = cn[j];
                if ((sj > msc) || (sj == msc && nj < mn)) r++;
            }
            rankOf[tid] = (short)r;
            smask[tid][0] = 0; smask[tid][1] = 0;
            smask[tid][2] = 0; smask[tid][3] = 0;
        }
        __syncthreads();

        for (int p = tid; p < M * M; p += 512) {
            int i = p / M, j = p - i * M;
            int ri = rankOf[i], rj = rankOf[j];
            if (rj > ri) {
                float iou = iou_f(bx1[i], by1[i], bx2[i], by2[i], bar[i],
                                  bx1[j], by1[j], bx2[j], by2[j], bar[j]);
                if (iou > NMS_THRESH_F)
                    atomicOr(&smask[ri][rj >> 5], 1u << (rj & 31));
            }
        }
        __syncthreads();

        unsigned k0, k1, k2, k3;
        k0 = (M >= 32)  ? 0xffffffffu : ((1u << M) - 1u);
        k1 = (M >= 64)  ? 0xffffffffu : (M > 32 ? ((1u << (M - 32)) - 1u) : 0u);
        k2 = (M >= 96)  ? 0xffffffffu : (M > 64 ? ((1u << (M - 64)) - 1u) : 0u);
        k3 = (M >= 128) ? 0xffffffffu : (M > 96 ? ((1u << (M - 96)) - 1u) : 0u);
        for (int r = 0; r < M; r++) {
            unsigned kw = (r < 32) ? k0 : (r < 64) ? k1 : (r < 96) ? k2 : k3;
            if ((kw >> (r & 31)) & 1u) {
                k0 &= ~smask[r][0];
                k1 &= ~smask[r][1];
                k2 &= ~smask[r][2];
                k3 &= ~smask[r][3];
            }
        }
        if (tid < M) {
            int r = rankOf[tid];
            unsigned kw = (r < 32) ? k0 : (r < 64) ? k1 : (r < 96) ? k2 : k3;
            if ((kw >> (r & 31)) & 1u)
                atomicMax(&g_best[b * NN + cn[tid]], pack_sl(cs[tid], c));
        }
    } else if (M > 128) {
        // ---- legacy path (essentially never) --------------------------------
        if (tid < M) {
            int n = cn[tid];
            const float* pb = props + (b * NN + n) * 4;
            const float* rg = reg + (size_t)(((b * NN + n) * CC) + c) * 4;
            decode_clip(pb, rg, bx1[tid], by1[tid], bx2[tid], by2[tid]);
            bar[tid] = (bx2[tid] - bx1[tid] + 1.0f) * (by2[tid] - by1[tid] + 1.0f);
            keep[tid] = 1;
            ord[tid] = tid;
        }
        int P = 1;
        while (P < M) P <<= 1;
        if (tid >= M && tid < P) { cs[tid] = -INFINITY; cn[tid] = 1 << 30; ord[tid] = tid; }
        __syncthreads();

        for (int k = 2; k <= P; k <<= 1) {
            for (int j = k >> 1; j > 0; j >>= 1) {
                if (tid < P) {
                    int ixj = tid ^ j;
                    if (ixj > tid) {
                        int a = ord[tid], bo = ord[ixj];
                        float sa = cs[a], sb = cs[bo];
                        bool pa = (sa > sb) || (sa == sb && cn[a] < cn[bo]);
                        bool desc = ((tid & k) == 0);
                        bool sw = desc ? !pa : pa;
                        if (sw) { ord[tid] = bo; ord[ixj] = a; }
                    }
                }
                __syncthreads();
            }
        }
        for (int i = 0; i < M - 1; i++) {
            __syncthreads();
            int oi = ord[i];
            if (!keep[oi]) continue;
            float ax1 = bx1[oi], ay1 = by1[oi], ax2 = bx2[oi], ay2 = by2[oi], aar = bar[oi];
            for (int t = i + 1 + tid; t < M; t += 512) {
                int ot = ord[t];
                if (!keep[ot]) continue;
                float iou = iou_f(ax1, ay1, ax2, ay2, aar,
                                  bx1[ot], by1[ot], bx2[ot], by2[ot], bar[ot]);
                if (iou > NMS_THRESH_F) keep[ot] = 0;
            }
        }
        __syncthreads();
        if (tid == 0) {
            int cum = 0;
            for (int t = 0; t < M; t++) {
                int ot = ord[t];
                if (keep[ot]) { if (++cum > TOPN_PER_CLS) keep[ot] = 0; }
            }
        }
        __syncthreads();
        if (tid < M && keep[tid])
            atomicMax(&g_best[b * NN + cn[tid]], pack_sl(cs[tid], c));
    }

    // ---- arrival + last-block select epilogue -------------------------------
    __threadfence();
    if (tid == 0) {
        unsigned old = atomicAdd(&g_done, 1u);
        lastFlag = (old == NTASKS - 1u) ? 1 : 0;
    }
    __syncthreads();
    if (!lastFlag) return;
    __threadfence();   // acquire: all g_best publications visible

    for (int bi = 0; bi < BB; bi++) {
        __syncthreads();                       // smem reuse (cs as vals)
        int n = tid;
        unsigned long long pk = g_best[bi * NN + n];
        float best = __uint_as_float((unsigned)(pk >> 32));
        int   lab  = CC - (int)(pk & 0xffffffffu);
        bool  v0   = pk != 0ull;

        cs[n] = v0 ? best : -1.0f;
        int num = __syncthreads_count(v0);

        // rank = #{j : vals[j] > mine}; broadcast smem reads
        float myv = cs[n];
        int rk = 0;
        #pragma unroll 8
        for (int j = 0; j < NN; j++)
            rk += (cs[j] > myv);

        // kth-largest = min{v : rank <= 99}
        float cand = (rk <= DET_PER_IMG - 1) ? myv : INFINITY;
        #pragma unroll
        for (int sft = 16; sft > 0; sft >>= 1)
            cand = fminf(cand, __shfl_xor_sync(0xffffffffu, cand, sft));
        if (lane == 0) wmin[wid] = cand;
        __syncthreads();
        if (tid < 32) {
            float c2 = (tid < 16) ? wmin[tid] : INFINITY;
            #pragma unroll
            for (int sft = 8; sft > 0; sft >>= 1)
                c2 = fminf(c2, __shfl_xor_sync(0xffffffffu, c2, sft));
            if (tid == 0) wmin[0] = c2;
        }
        __syncthreads();
        float thr = (num > DET_PER_IMG) ? wmin[0] : -1.0f;
        bool det = v0 && (best >= thr);

        float X1 = 0.f, Y1 = 0.f, X2 = 0.f, Y2 = 0.f, sc = 0.f, lb = 0.f, dv = 0.f;
        if (det) {
            const float* pb = props + (bi * NN + n) * 4;
            const float* rg = reg + (size_t)(((bi * NN + n) * CC) + lab) * 4;
            decode_clip(pb, rg, X1, Y1, X2, Y2);
            sc = best; lb = (float)lab; dv = 1.f;
        }
        int idx = bi * NN + n;
        out[OFF_BOXES + idx * 4 + 0] = X1;
        out[OFF_BOXES + idx * 4 + 1] = Y1;
        out[OFF_BOXES + idx * 4 + 2] = X2;
        out[OFF_BOXES + idx * 4 + 3] = Y2;
        out[OFF_SCORES + idx] = sc;
        out[OFF_LABELS + idx] = lb;
        out[OFF_VALID  + idx] = dv;
        g_validf[idx] = dv;
    }
    if (tid == 0) atomicExch(&g_done, 0u);     // reset for next graph replay
}

// ---------------------------------------------------------------------------
// K3: features * det_valid  (memory-bound, float4)
// ---------------------------------------------------------------------------
__global__ __launch_bounds__(256) void k_feats(const float4* __restrict__ f,
                                               float4* __restrict__ out)
{
    int i = blockIdx.x * blockDim.x + threadIdx.x;
    if (i >= SZ_FEATS / 4) return;
    float m = g_validf[i >> 10];     // DD/4 = 1024 float4 per row
    float4 v = f[i];
    v.x *= m; v.y *= m; v.z *= m; v.w *= m;
    out[i] = v;
}

// ---------------------------------------------------------------------------
extern "C" void kernel_launch(void* const* d_in, const int* in_sizes, int n_in,
                              void* d_out, int out_size)
{
    const float *logits = nullptr, *reg = nullptr, *props = nullptr, *feats = nullptr;
    for (int i = 0; i < n_in; i++) {
        switch (in_sizes[i]) {
            case SZ_LOGITS: logits = (const float*)d_in[i]; break;
            case SZ_REG:    reg    = (const float*)d_in[i]; break;
            case SZ_PROPS:  props  = (const float*)d_in[i]; break;
            case SZ_FEATS:  feats  = (const float*)d_in[i]; break;
            default: break;
        }
    }
    float* out = (float*)d_out;

    k_reduce<<<128, 256>>>(logits);
    k_nms<<<NTASKS, 512>>>(logits, reg, props, out);
    k_feats<<<(SZ_FEATS / 4 + 255) / 256, 256>>>((const float4*)feats,
                                                 (float4*)(out + OFF_FEATS));
    (void)out_size;
}